// round 15
// baseline (speedup 1.0000x reference)
#include <cuda_runtime.h>

#define KC 32
#define LC 64
#define HC 256
#define OC 32
#define BMAX 256
#define NMAX 100000
#define NB 128            // histogram / scatter blocks
#define CPG 4             // CTAs per graph
#define CHUNK 64          // nodes per CTA chunk
#define HS 264            // hbuf row stride (floats)

#define ZW1_SMEM ((LC*HC + 4*LC) * 4)
#define MAIN_SMEM ((KC*HC + CHUNK*HS) * 4)   // zw1s + hbuf = 100,352 B

typedef unsigned long long u64;

__device__ __forceinline__ u64 fma2(u64 a, u64 b, u64 c) {
    u64 d;
    asm("fma.rn.f32x2 %0, %1, %2, %3;" : "=l"(d) : "l"(a), "l"(b), "l"(c));
    return d;
}
__device__ __forceinline__ u64 pack2(float lo, float hi) {
    u64 d;
    asm("mov.b64 %0, {%1, %2};" : "=l"(d) : "f"(lo), "f"(hi));
    return d;
}
__device__ __forceinline__ void unpack2(u64 v, float& lo, float& hi) {
    asm("mov.b64 {%0, %1}, %2;" : "=f"(lo), "=f"(hi) : "l"(v));
}

// ---------------- device scratch ------------------------------------------
__device__ float g_zw1[BMAX * KC * HC];    // 8 MB: z @ W1
__device__ float g_w2q[HC * OC];           // W2 packed [q][o][4j], q=j/4
__device__ int   g_perm[NMAX];
__device__ int   g_hist[BMAX];
__device__ int   g_cnt[BMAX];
__device__ int   g_binstart[BMAX];
__device__ int   g_cursor[BMAX];
__device__ int   g_bh[NB * BMAX];          // per-block histograms

// ---------------- 1. prep: zW1 GEMM | W2 pack | per-block hist -------------
__global__ void prep_kernel(const float* __restrict__ z,
                            const float* __restrict__ W1,
                            const float* __restrict__ W2,
                            const int* __restrict__ batch,
                            int n, int B, int zb) {
    int tid = threadIdx.x;
    int bx = blockIdx.x;

    if (bx == zb + NB) {
        // W2 pack: float4 idx -> [q][o][4]: v = W2[4q..4q+3][o]
        #pragma unroll
        for (int e = 0; e < 8; e++) {
            int idx = e * 256 + tid;       // 0..2047
            int q = idx >> 5, o = idx & 31;
            float4 v;
            v.x = W2[(4 * q + 0) * OC + o];
            v.y = W2[(4 * q + 1) * OC + o];
            v.z = W2[(4 * q + 2) * OC + o];
            v.w = W2[(4 * q + 3) * OC + o];
            ((float4*)g_w2q)[idx] = v;
        }
        return;
    }
    if (bx >= zb) {
        __shared__ int sh[BMAX];
        int blk = bx - zb;
        sh[tid] = 0;
        __syncthreads();
        int span = (n + NB - 1) / NB;
        int lo = blk * span, hi = min(n, lo + span);
        for (int i = lo + tid; i < hi; i += 256) {
            int b = batch[i];
            if (b >= 0 && b < B) atomicAdd(&sh[b], 1);
        }
        __syncthreads();
        g_bh[blk * BMAX + tid] = sh[tid];
        if (sh[tid]) atomicAdd(&g_hist[tid], sh[tid]);
        return;
    }
    extern __shared__ __align__(16) float sm[];
    float* w1s = sm;              // LC*HC
    float* zs  = sm + LC * HC;    // 4*LC

    for (int i = tid; i < (LC * HC) / 4; i += 256)
        ((float4*)w1s)[i] = ((const float4*)W1)[i];

    int rows = zb * 16;
    int row0 = bx * 16;
    for (int g = 0; g < 4; g++) {
        int rbase = row0 + g * 4;
        __syncthreads();
        int rr = tid >> 6, ll = tid & 63;
        if (rbase + rr < rows)
            zs[rr * LC + ll] = z[(size_t)(rbase + rr) * LC + ll];
        __syncthreads();

        float a0 = 0.f, a1 = 0.f, a2 = 0.f, a3 = 0.f;
        #pragma unroll
        for (int l = 0; l < LC; l++) {
            float w = w1s[l * HC + tid];
            a0 += zs[0 * LC + l] * w;
            a1 += zs[1 * LC + l] * w;
            a2 += zs[2 * LC + l] * w;
            a3 += zs[3 * LC + l] * w;
        }
        if (rbase + 3 < rows) {
            g_zw1[(size_t)(rbase + 0) * HC + tid] = a0;
            g_zw1[(size_t)(rbase + 1) * HC + tid] = a1;
            g_zw1[(size_t)(rbase + 2) * HC + tid] = a2;
            g_zw1[(size_t)(rbase + 3) * HC + tid] = a3;
        }
    }
}

// ---------------- 2. scan ---------------------------------------------------
__global__ void scan_kernel() {
    __shared__ int tmp[BMAX];
    int tid = threadIdx.x;
    int v0 = g_hist[tid];
    g_cnt[tid]  = v0;
    g_hist[tid] = 0;               // idempotent across graph replays
    tmp[tid] = v0;
    __syncthreads();
    for (int d = 1; d < BMAX; d <<= 1) {
        int v = (tid >= d) ? tmp[tid - d] : 0;
        __syncthreads();
        tmp[tid] += v;
        __syncthreads();
    }
    int start = tmp[tid] - v0;
    g_binstart[tid] = start;
    g_cursor[tid]   = start;
}

// ---------------- 3. scatter ------------------------------------------------
__global__ void scatter_kernel(const int* __restrict__ batch, int n, int B) {
    __shared__ int cur[BMAX];
    int tid = threadIdx.x, blk = blockIdx.x;
    int mine = g_bh[blk * BMAX + tid];
    cur[tid] = mine ? atomicAdd(&g_cursor[tid], mine) : 0;   // spread atomics
    __syncthreads();
    int span = (n + NB - 1) / NB;
    int lo = blk * span, hi = min(n, lo + span);
    for (int i = lo + tid; i < hi; i += 256) {
        int b = batch[i];
        if (b < 0 || b >= B) continue;
        int pos = atomicAdd(&cur[b], 1);    // smem atomic
        g_perm[pos] = i;
    }
}

// ---------------- 4. main fused kernel --------------------------------------
// H   phase (unchanged tile): warp(nh,jw): 32n x 64j; lane(ng,jg): 8n x 8j.
//     s + perm read directly via LDG (L1), zW1 from smem.
// OUT phase (new): warp w owns nodes w*8..w*8+7, lane = o (0..31).
//     h via single-address broadcast LDS.128 (1 wf), W2 via packed LDG.128.
//     No partial buffers, no reduction phase. 2 syncs per chunk.
__global__ __launch_bounds__(256, 2)
void main_kernel(const float* __restrict__ s,
                 const float* __restrict__ b1, const float* __restrict__ b2,
                 float* __restrict__ out, int B) {
    extern __shared__ __align__(16) float sm[];
    float* zw1s = sm;                        // [k][j] 32x256 = 8192 fl
    float* hbuf = zw1s + KC * HC;            // [n][HS]        16896 fl

    int tid = threadIdx.x;
    int b   = blockIdx.x % B;
    int c0  = blockIdx.x / B;
    int cnt = g_cnt[b];
    if (c0 * CHUNK >= cnt) return;
    int start = g_binstart[b];

    // prologue: stage per-graph zW1 (first loop-top sync publishes it)
    const float4* zw1g = (const float4*)(g_zw1 + (size_t)b * KC * HC);
    #pragma unroll
    for (int i = 0; i < 8; i++)
        ((float4*)zw1s)[tid + i * 256] = zw1g[tid + i * 256];

    int w = tid >> 5, lane = tid & 31;
    int nh = w & 1, jw = w >> 1;     // H roles
    int ng = lane >> 3, jg = lane & 7;
    int j0 = jw * 64 + jg * 4;
    int j1 = j0 + 32;
    int nrow0 = nh * 32 + ng;        // H nodes: nrow0 + 4*t

    // b1 bias quads (packed) + b2 scalar (OUT lane = o)
    u64 bq[4];
    {
        float4 v = *(const float4*)&b1[j0];
        bq[0] = pack2(v.x, v.y); bq[1] = pack2(v.z, v.w);
        v = *(const float4*)&b1[j1];
        bq[2] = pack2(v.x, v.y); bq[3] = pack2(v.z, v.w);
    }
    float b2v = __ldg(b2 + lane);

    for (int c = c0; c * CHUNK < cnt; c += CPG) {
        int nbase = c * CHUNK;
        __syncthreads();             // hbuf safe to rewrite (+prologue on iter 1)

        // ---- node ids for H (this lane's 8 nodes, dedup'd across jg lanes)
        int nidh[8];
        #pragma unroll
        for (int t = 0; t < 8; t++) {
            int gi = nbase + nrow0 + 4 * t;
            nidh[t] = (gi < cnt) ? __ldg(g_perm + start + gi) : -1;
        }

        // ================= H phase =================
        u64 ha[8][4];
        #pragma unroll
        for (int t = 0; t < 8; t++) {
            ha[t][0] = bq[0]; ha[t][1] = bq[1];
            ha[t][2] = bq[2]; ha[t][3] = bq[3];
        }
        #pragma unroll
        for (int kg = 0; kg < 8; kg++) {
            float4 s4[8];
            #pragma unroll
            for (int t = 0; t < 8; t++)
                s4[t] = (nidh[t] >= 0)
                    ? __ldg((const float4*)(s + (size_t)nidh[t] * KC + kg * 4))
                    : make_float4(0.f, 0.f, 0.f, 0.f);
            #pragma unroll
            for (int kk = 0; kk < 4; kk++) {
                int k = kg * 4 + kk;
                ulonglong2 wa = *(const ulonglong2*)&zw1s[k * HC + j0];
                ulonglong2 wb = *(const ulonglong2*)&zw1s[k * HC + j1];
                #pragma unroll
                for (int t = 0; t < 8; t++) {
                    float sv = ((const float*)&s4[t])[kk];
                    u64 sp = pack2(sv, sv);
                    ha[t][0] = fma2(sp, wa.x, ha[t][0]);
                    ha[t][1] = fma2(sp, wa.y, ha[t][1]);
                    ha[t][2] = fma2(sp, wb.x, ha[t][2]);
                    ha[t][3] = fma2(sp, wb.y, ha[t][3]);
                }
            }
        }
        // relu + store h (node-major)
        #pragma unroll
        for (int t = 0; t < 8; t++) {
            int nt = nrow0 + 4 * t;
            float4 v0, v1; float x, y;
            unpack2(ha[t][0], x, y); v0.x = fmaxf(x,0.f); v0.y = fmaxf(y,0.f);
            unpack2(ha[t][1], x, y); v0.z = fmaxf(x,0.f); v0.w = fmaxf(y,0.f);
            unpack2(ha[t][2], x, y); v1.x = fmaxf(x,0.f); v1.y = fmaxf(y,0.f);
            unpack2(ha[t][3], x, y); v1.z = fmaxf(x,0.f); v1.w = fmaxf(y,0.f);
            *(float4*)&hbuf[nt * HS + j0] = v0;
            *(float4*)&hbuf[nt * HS + j1] = v1;
        }
        __syncthreads();

        // ================= OUT phase: warp w -> nodes w*8..+7, lane = o ====
        int nido[8];
        #pragma unroll
        for (int t = 0; t < 8; t++) {
            int gi = nbase + w * 8 + t;
            nido[t] = (gi < cnt) ? __ldg(g_perm + start + gi) : -1;
        }
        u64 acc[8];
        #pragma unroll
        for (int t = 0; t < 8; t++) acc[t] = 0ull;

        const float* hrow = hbuf + (w * 8) * HS;
        #pragma unroll 4
        for (int q = 0; q < HC / 4; q++) {
            // packed W2 rows 4q..4q+3 for this lane's o: 16B, L1-resident
            ulonglong2 wv = __ldg((const ulonglong2*)(g_w2q + q * 128 + lane * 4));
            #pragma unroll
            for (int t = 0; t < 8; t++) {
                // broadcast: single address across the warp -> 1 wavefront
                ulonglong2 hv = *(const ulonglong2*)&hrow[t * HS + q * 4];
                acc[t] = fma2(hv.x, wv.x, acc[t]);   // lo: j=4q,   hi: j=4q+1
                acc[t] = fma2(hv.y, wv.y, acc[t]);   // lo: j=4q+2, hi: j=4q+3
            }
        }
        #pragma unroll
        for (int t = 0; t < 8; t++) {
            if (nido[t] >= 0) {
                float lo, hi;
                unpack2(acc[t], lo, hi);
                out[(size_t)nido[t] * OC + lane] = lo + hi + b2v;  // coalesced
            }
        }
    }
}

// ---------------- launch ----------------------------------------------------
extern "C" void kernel_launch(void* const* d_in, const int* in_sizes, int n_in,
                              void* d_out, int out_size) {
    const float* z     = (const float*)d_in[0];
    const float* s     = (const float*)d_in[1];
    const int*   batch = (const int*)d_in[2];   // JAX x64 disabled -> int32
    const float* W1    = (const float*)d_in[3];
    const float* b1    = (const float*)d_in[4];
    const float* W2    = (const float*)d_in[5];
    const float* b2    = (const float*)d_in[6];
    float*       out   = (float*)d_out;

    int n = in_sizes[2];
    int B = in_sizes[0] / (KC * LC);
    int zb = (B * KC + 15) / 16;

    cudaFuncSetAttribute(prep_kernel,
        cudaFuncAttributeMaxDynamicSharedMemorySize, ZW1_SMEM);
    cudaFuncSetAttribute(main_kernel,
        cudaFuncAttributeMaxDynamicSharedMemorySize, MAIN_SMEM);

    prep_kernel<<<zb + NB + 1, 256, ZW1_SMEM>>>(z, W1, W2, batch, n, B, zb);
    scan_kernel<<<1, BMAX>>>();
    scatter_kernel<<<NB, 256>>>(batch, n, B);
    main_kernel<<<B * CPG, 256, MAIN_SMEM>>>(s, b1, b2, out, B);
}

// round 16
// speedup vs baseline: 1.4518x; 1.4518x over previous
#include <cuda_runtime.h>

#define KC 32
#define LC 64
#define HC 256
#define OC 32
#define BMAX 256
#define NMAX 100000
#define NB 128            // histogram / scatter blocks
#define CPG 4             // CTAs per graph
#define CHUNK 64          // nodes per CTA chunk
#define SS 36             // ss row stride (floats)
#define HS 264            // hbuf row stride (floats): HS%32==8 -> OUT loads conflict-free
#define PS 36             // pbuf row stride (floats)

#define ZW1_SMEM ((LC*HC + 4*LC) * 4)
// zw1s + ss + hbuf (pbuf aliases hbuf) + nids (now correctly included)
#define MAIN_FLOATS (KC*HC + CHUNK*SS + CHUNK*HS)
#define MAIN_SMEM (MAIN_FLOATS*4 + CHUNK*4)

typedef unsigned long long u64;

__device__ __forceinline__ u64 fma2(u64 a, u64 b, u64 c) {
    u64 d;
    asm("fma.rn.f32x2 %0, %1, %2, %3;" : "=l"(d) : "l"(a), "l"(b), "l"(c));
    return d;
}
__device__ __forceinline__ u64 pack2(float lo, float hi) {
    u64 d;
    asm("mov.b64 %0, {%1, %2};" : "=l"(d) : "f"(lo), "f"(hi));
    return d;
}
__device__ __forceinline__ void unpack2(u64 v, float& lo, float& hi) {
    asm("mov.b64 {%0, %1}, %2;" : "=f"(lo), "=f"(hi) : "l"(v));
}

// ---------------- device scratch ------------------------------------------
__device__ float g_zw1[BMAX * KC * HC];    // 8 MB: z @ W1
__device__ int   g_perm[NMAX];
__device__ int   g_hist[BMAX];             // zeroed by main CTA0 each replay
__device__ int   g_cnt[BMAX];
__device__ int   g_binstart[BMAX];
__device__ int   g_cur2[BMAX];             // scatter reservation counters
__device__ int   g_bh[NB * BMAX];          // per-block histograms

// ---------------- 1. prep: zW1 GEMM | per-block hist -----------------------
__global__ void prep_kernel(const float* __restrict__ z,
                            const float* __restrict__ W1,
                            const int* __restrict__ batch,
                            int n, int B, int zb) {
    int tid = threadIdx.x;
    int bx = blockIdx.x;

    if (bx >= zb) {
        __shared__ int sh[BMAX];
        int blk = bx - zb;
        sh[tid] = 0;
        __syncthreads();
        int span = (n + NB - 1) / NB;
        int lo = blk * span, hi = min(n, lo + span);
        for (int i = lo + tid; i < hi; i += 256) {
            int b = batch[i];
            if (b >= 0 && b < B) atomicAdd(&sh[b], 1);
        }
        __syncthreads();
        g_bh[blk * BMAX + tid] = sh[tid];
        if (sh[tid]) atomicAdd(&g_hist[tid], sh[tid]);
        return;
    }
    extern __shared__ __align__(16) float sm[];
    float* w1s = sm;              // LC*HC
    float* zs  = sm + LC * HC;    // 4*LC

    for (int i = tid; i < (LC * HC) / 4; i += 256)
        ((float4*)w1s)[i] = ((const float4*)W1)[i];

    int rows = zb * 16;
    int row0 = bx * 16;
    for (int g = 0; g < 4; g++) {
        int rbase = row0 + g * 4;
        __syncthreads();
        int rr = tid >> 6, ll = tid & 63;
        if (rbase + rr < rows)
            zs[rr * LC + ll] = z[(size_t)(rbase + rr) * LC + ll];
        __syncthreads();

        float a0 = 0.f, a1 = 0.f, a2 = 0.f, a3 = 0.f;
        #pragma unroll
        for (int l = 0; l < LC; l++) {
            float w = w1s[l * HC + tid];
            a0 += zs[0 * LC + l] * w;
            a1 += zs[1 * LC + l] * w;
            a2 += zs[2 * LC + l] * w;
            a3 += zs[3 * LC + l] * w;
        }
        if (rbase + 3 < rows) {
            g_zw1[(size_t)(rbase + 0) * HC + tid] = a0;
            g_zw1[(size_t)(rbase + 1) * HC + tid] = a1;
            g_zw1[(size_t)(rbase + 2) * HC + tid] = a2;
            g_zw1[(size_t)(rbase + 3) * HC + tid] = a3;
        }
    }
}

// ---------------- 2. scatter (scan fused: each block recomputes it) --------
__global__ void scatter_kernel(const int* __restrict__ batch, int n, int B) {
    __shared__ int tmp[BMAX];
    __shared__ int cur[BMAX];
    int tid = threadIdx.x, blk = blockIdx.x;

    int v0 = g_hist[tid];
    tmp[tid] = v0;
    __syncthreads();
    #pragma unroll
    for (int d = 1; d < BMAX; d <<= 1) {
        int v = (tid >= d) ? tmp[tid - d] : 0;
        __syncthreads();
        tmp[tid] += v;
        __syncthreads();
    }
    int start = tmp[tid] - v0;     // exclusive scan
    if (blk == 0) {                // publish for main
        g_binstart[tid] = start;
        g_cnt[tid]      = v0;
    }
    int mine = g_bh[blk * BMAX + tid];
    cur[tid] = start + (mine ? atomicAdd(&g_cur2[tid], mine) : 0);
    __syncthreads();

    int span = (n + NB - 1) / NB;
    int lo = blk * span, hi = min(n, lo + span);
    for (int i = lo + tid; i < hi; i += 256) {
        int b = batch[i];
        if (b < 0 || b >= B) continue;
        int pos = atomicAdd(&cur[b], 1);    // smem atomic
        g_perm[pos] = i;
    }
}

// ---------------- 3. main fused kernel --------------------------------------
// H   phase: warp(nh,jw): 32n x 64j; lane(ng,jg): 8n x 8j. zW1+s from smem.
// OUT phase: warp(nh,q=jw): 32n x 32o over 64j; lane(ng,og): 8n x 4o.
//   hbuf loads conflict-free (HS%32==8); partials reduced via aliased pbuf.
__global__ __launch_bounds__(256, 2)
void main_kernel(const float* __restrict__ s, const float* __restrict__ W2,
                 const float* __restrict__ b1, const float* __restrict__ b2,
                 float* __restrict__ out, int B) {
    extern __shared__ __align__(16) float sm[];
    float* zw1s = sm;                        // [k][j]  32x256 = 8192 fl
    float* ss   = zw1s + KC * HC;            // [n][SS]         2304 fl
    float* hbuf = ss + CHUNK * SS;           // [n][HS]        16896 fl
    float* pbuf = hbuf;                      // alias (sync-separated)
    int*   nids = (int*)(hbuf + CHUNK * HS); // CHUNK ints (inside MAIN_SMEM)

    int tid = threadIdx.x;
    // replay idempotency: zero hist + reservation counters for next replay
    if (blockIdx.x == 0) { g_hist[tid] = 0; g_cur2[tid] = 0; }

    int b   = blockIdx.x % B;
    int c0  = blockIdx.x / B;
    int cnt = g_cnt[b];
    if (c0 * CHUNK >= cnt) return;
    int start = g_binstart[b];

    // prologue: stage per-graph zW1
    const float4* zw1g = (const float4*)(g_zw1 + (size_t)b * KC * HC);
    #pragma unroll
    for (int i = 0; i < 8; i++)
        ((float4*)zw1s)[tid + i * 256] = zw1g[tid + i * 256];

    int w = tid >> 5, lane = tid & 31;
    int nh = w & 1, jw = w >> 1;     // roles (both phases)
    int ng = lane >> 3, jg = lane & 7;
    int j0 = jw * 64 + jg * 4;
    int j1 = j0 + 32;
    int nrow0 = nh * 32 + ng;        // node = nrow0 + 4*t

    // b1 bias quads (packed); b2 quad for the final phase (fixed per thread)
    u64 bq[4];
    {
        float4 v = *(const float4*)&b1[j0];
        bq[0] = pack2(v.x, v.y); bq[1] = pack2(v.z, v.w);
        v = *(const float4*)&b1[j1];
        bq[2] = pack2(v.x, v.y); bq[3] = pack2(v.z, v.w);
    }
    float4 bb = __ldg((const float4*)(b2 + ((tid & 7) * 4)));

    // perm prefetch (hidden behind whatever precedes the loop-top sync)
    int pfn[2];
    {
        #pragma unroll
        for (int e = 0; e < 2; e++) {
            int i = ((e * 256 + tid) >> 3);
            int gi = c0 * CHUNK + i;
            pfn[e] = (gi < cnt) ? __ldg(g_perm + start + gi) : -1;
        }
    }

    for (int c = c0; c * CHUNK < cnt; c += CPG) {
        __syncthreads();             // protects ss/nids/hbuf reuse (+prologue)
        // stage nids + s rows (512 float4, 2 per thread), using prefetched ids
        #pragma unroll
        for (int e = 0; e < 2; e++) {
            int idx = e * 256 + tid;
            int i = idx >> 3, qq = idx & 7;
            int nid = pfn[e];
            if (qq == 0) nids[i] = nid;
            float4 v = make_float4(0.f, 0.f, 0.f, 0.f);
            if (nid >= 0) v = __ldg((const float4*)(s + (size_t)nid * KC) + qq);
            *(float4*)&ss[i * SS + qq * 4] = v;
        }
        // prefetch next chunk's perm ids (latency hidden behind H+OUT)
        {
            int cn = c + CPG;
            #pragma unroll
            for (int e = 0; e < 2; e++) {
                int i = ((e * 256 + tid) >> 3);
                int gi = cn * CHUNK + i;
                pfn[e] = (cn * CHUNK < cnt && gi < cnt)
                       ? __ldg(g_perm + start + gi) : -1;
            }
        }
        __syncthreads();

        // ================= H phase =================
        u64 ha[8][4];
        #pragma unroll
        for (int t = 0; t < 8; t++) {
            ha[t][0] = bq[0]; ha[t][1] = bq[1];
            ha[t][2] = bq[2]; ha[t][3] = bq[3];
        }
        #pragma unroll
        for (int kg = 0; kg < 8; kg++) {
            float4 s4[8];
            #pragma unroll
            for (int t = 0; t < 8; t++)
                s4[t] = *(const float4*)&ss[(nrow0 + 4 * t) * SS + kg * 4];
            #pragma unroll
            for (int kk = 0; kk < 4; kk++) {
                int k = kg * 4 + kk;
                ulonglong2 wa = *(const ulonglong2*)&zw1s[k * HC + j0];
                ulonglong2 wb = *(const ulonglong2*)&zw1s[k * HC + j1];
                #pragma unroll
                for (int t = 0; t < 8; t++) {
                    float sv = ((const float*)&s4[t])[kk];
                    u64 sp = pack2(sv, sv);
                    ha[t][0] = fma2(sp, wa.x, ha[t][0]);
                    ha[t][1] = fma2(sp, wa.y, ha[t][1]);
                    ha[t][2] = fma2(sp, wb.x, ha[t][2]);
                    ha[t][3] = fma2(sp, wb.y, ha[t][3]);
                }
            }
        }
        // relu + store h (node-major)
        #pragma unroll
        for (int t = 0; t < 8; t++) {
            int nt = nrow0 + 4 * t;
            float4 v0, v1; float x, y;
            unpack2(ha[t][0], x, y); v0.x = fmaxf(x,0.f); v0.y = fmaxf(y,0.f);
            unpack2(ha[t][1], x, y); v0.z = fmaxf(x,0.f); v0.w = fmaxf(y,0.f);
            unpack2(ha[t][2], x, y); v1.x = fmaxf(x,0.f); v1.y = fmaxf(y,0.f);
            unpack2(ha[t][3], x, y); v1.z = fmaxf(x,0.f); v1.w = fmaxf(y,0.f);
            *(float4*)&hbuf[nt * HS + j0] = v0;
            *(float4*)&hbuf[nt * HS + j1] = v1;
        }
        __syncthreads();

        // ================= OUT phase (j-quarter q = jw) =================
        u64 acc[8][2];
        #pragma unroll
        for (int t = 0; t < 8; t++) { acc[t][0] = 0ull; acc[t][1] = 0ull; }
        #pragma unroll 4
        for (int j4 = 0; j4 < 16; j4++) {
            int jb = jw * 64 + j4 * 4;
            ulonglong2 w20 = __ldg((const ulonglong2*)(W2 + (jb + 0) * OC + jg * 4));
            ulonglong2 w21 = __ldg((const ulonglong2*)(W2 + (jb + 1) * OC + jg * 4));
            ulonglong2 w22 = __ldg((const ulonglong2*)(W2 + (jb + 2) * OC + jg * 4));
            ulonglong2 w23 = __ldg((const ulonglong2*)(W2 + (jb + 3) * OC + jg * 4));
            #pragma unroll
            for (int t = 0; t < 8; t++) {
                int nt = nrow0 + 4 * t;
                float4 hv = *(const float4*)&hbuf[nt * HS + jb];
                u64 h0 = pack2(hv.x, hv.x), h1 = pack2(hv.y, hv.y);
                u64 h2 = pack2(hv.z, hv.z), h3 = pack2(hv.w, hv.w);
                acc[t][0] = fma2(h0, w20.x, acc[t][0]);
                acc[t][1] = fma2(h0, w20.y, acc[t][1]);
                acc[t][0] = fma2(h1, w21.x, acc[t][0]);
                acc[t][1] = fma2(h1, w21.y, acc[t][1]);
                acc[t][0] = fma2(h2, w22.x, acc[t][0]);
                acc[t][1] = fma2(h2, w22.y, acc[t][1]);
                acc[t][0] = fma2(h3, w23.x, acc[t][0]);
                acc[t][1] = fma2(h3, w23.y, acc[t][1]);
            }
        }
        __syncthreads();     // all hbuf reads done before pbuf (alias) writes
        #pragma unroll
        for (int t = 0; t < 8; t++) {
            int nt = nrow0 + 4 * t;
            float4 v;
            unpack2(acc[t][0], v.x, v.y);
            unpack2(acc[t][1], v.z, v.w);
            *(float4*)&pbuf[(jw * CHUNK + nt) * PS + jg * 4] = v;
        }
        __syncthreads();

        // final: sum 4 quarters + b2, store (512 float4, 2 per thread)
        #pragma unroll
        for (int e = 0; e < 2; e++) {
            int idx = e * 256 + tid;
            int nn = idx >> 3, oo = (idx & 7) * 4;
            int nid = nids[nn];
            if (nid >= 0) {
                float4 r  = *(const float4*)&pbuf[(0 * CHUNK + nn) * PS + oo];
                float4 p1 = *(const float4*)&pbuf[(1 * CHUNK + nn) * PS + oo];
                float4 p2 = *(const float4*)&pbuf[(2 * CHUNK + nn) * PS + oo];
                float4 p3 = *(const float4*)&pbuf[(3 * CHUNK + nn) * PS + oo];
                r.x += p1.x + p2.x + p3.x + bb.x;
                r.y += p1.y + p2.y + p3.y + bb.y;
                r.z += p1.z + p2.z + p3.z + bb.z;
                r.w += p1.w + p2.w + p3.w + bb.w;
                *(float4*)(out + (size_t)nid * OC + oo) = r;
            }
        }
    }
}

// ---------------- launch ----------------------------------------------------
extern "C" void kernel_launch(void* const* d_in, const int* in_sizes, int n_in,
                              void* d_out, int out_size) {
    const float* z     = (const float*)d_in[0];
    const float* s     = (const float*)d_in[1];
    const int*   batch = (const int*)d_in[2];   // JAX x64 disabled -> int32
    const float* W1    = (const float*)d_in[3];
    const float* b1    = (const float*)d_in[4];
    const float* W2    = (const float*)d_in[5];
    const float* b2    = (const float*)d_in[6];
    float*       out   = (float*)d_out;

    int n = in_sizes[2];
    int B = in_sizes[0] / (KC * LC);
    int zb = (B * KC + 15) / 16;

    cudaFuncSetAttribute(prep_kernel,
        cudaFuncAttributeMaxDynamicSharedMemorySize, ZW1_SMEM);
    cudaFuncSetAttribute(main_kernel,
        cudaFuncAttributeMaxDynamicSharedMemorySize, MAIN_SMEM);

    prep_kernel<<<zb + NB, 256, ZW1_SMEM>>>(z, W1, batch, n, B, zb);
    scatter_kernel<<<NB, 256>>>(batch, n, B);
    main_kernel<<<B * CPG, 256, MAIN_SMEM>>>(s, W2, b1, b2, out, B);
}

// round 17
// speedup vs baseline: 1.5655x; 1.0783x over previous
#include <cuda_runtime.h>

#define KC 32
#define LC 64
#define HC 256
#define OC 32
#define BMAX 256
#define NMAX 100000
#define NB 128            // histogram / scatter blocks
#define CPG 4             // CTAs per graph
#define CHUNK 64          // nodes per CTA chunk
#define SS 36             // ss row stride (floats)
#define HS 264            // hbuf row stride (floats): HS%32==8 -> OUT loads conflict-free
#define PS 36             // pbuf row stride (floats)
#define ZROWS 64          // zW1 rows per prep block

#define PREP_SMEM ((LC*HC + ZROWS*LC) * 4)     // W1 (64KB) + z rows (16KB)
#define MAIN_FLOATS (KC*HC + CHUNK*SS + CHUNK*HS)
#define MAIN_SMEM (MAIN_FLOATS*4 + CHUNK*4)

typedef unsigned long long u64;

__device__ __forceinline__ u64 fma2(u64 a, u64 b, u64 c) {
    u64 d;
    asm("fma.rn.f32x2 %0, %1, %2, %3;" : "=l"(d) : "l"(a), "l"(b), "l"(c));
    return d;
}
__device__ __forceinline__ u64 pack2(float lo, float hi) {
    u64 d;
    asm("mov.b64 %0, {%1, %2};" : "=l"(d) : "f"(lo), "f"(hi));
    return d;
}
__device__ __forceinline__ void unpack2(u64 v, float& lo, float& hi) {
    asm("mov.b64 {%0, %1}, %2;" : "=f"(lo), "=f"(hi) : "l"(v));
}

// ---------------- device scratch ------------------------------------------
__device__ float g_zw1[BMAX * KC * HC];    // 8 MB: z @ W1
__device__ int   g_perm[NMAX];
__device__ int   g_hist[BMAX];             // zeroed by main CTA0 each replay
__device__ int   g_cnt[BMAX];
__device__ int   g_binstart[BMAX];
__device__ int   g_cur2[BMAX];             // scatter reservation counters
__device__ int   g_bh[NB * BMAX];          // per-block histograms

// ---------------- 1. prep: zW1 GEMM (fma2, 64 rows/blk) | per-block hist ---
__global__ void prep_kernel(const float* __restrict__ z,
                            const float* __restrict__ W1,
                            const int* __restrict__ batch,
                            int n, int B, int zb2) {
    int tid = threadIdx.x;
    int bx = blockIdx.x;

    if (bx >= zb2) {
        // ---- per-block histogram + global histogram ----
        __shared__ int sh[BMAX];
        int blk = bx - zb2;
        sh[tid] = 0;
        __syncthreads();
        int span = (n + NB - 1) / NB;
        int lo = blk * span, hi = min(n, lo + span);
        for (int i = lo + tid; i < hi; i += 256) {
            int b = batch[i];
            if (b >= 0 && b < B) atomicAdd(&sh[b], 1);
        }
        __syncthreads();
        g_bh[blk * BMAX + tid] = sh[tid];
        if (sh[tid]) atomicAdd(&g_hist[tid], sh[tid]);
        return;
    }

    // ---- zW1 = z @ W1 : 64 rows per block, fma2 on j-pairs ----
    extern __shared__ __align__(16) float sm[];
    float* w1s = sm;              // LC*HC floats (u64 view: [l][jp])
    float* zs  = sm + LC * HC;    // ZROWS*LC floats

    int rows = B * KC;
    int row0 = bx * ZROWS;

    // stage W1 (4096 float4, 16 per thread, contiguous)
    #pragma unroll
    for (int e = 0; e < 16; e++)
        ((float4*)w1s)[e * 256 + tid] = ((const float4*)W1)[e * 256 + tid];
    // stage z rows (1024 float4, 4 per thread), zero-guard the tail
    #pragma unroll
    for (int e = 0; e < 4; e++) {
        int i = e * 256 + tid;               // float4 idx within 64 rows
        int lrow = i >> 4;                   // 16 float4 per row
        float4 v = make_float4(0.f, 0.f, 0.f, 0.f);
        if (row0 + lrow < rows)
            v = ((const float4*)z)[(size_t)row0 * (LC / 4) + i];
        ((float4*)zs)[i] = v;
    }
    __syncthreads();

    int jp = tid & 127;          // j-pair index (j = 2*jp, 2*jp+1)
    int rh = tid >> 7;           // row-half within each 8-row group

    #pragma unroll
    for (int rg = 0; rg < 8; rg++) {
        int rb = rg * 8 + rh * 4;            // local row base (4 rows)
        u64 a0 = 0ull, a1 = 0ull, a2 = 0ull, a3 = 0ull;
        #pragma unroll 4
        for (int lg = 0; lg < LC / 4; lg++) {
            float4 s0 = *(const float4*)&zs[(rb + 0) * LC + lg * 4];
            float4 s1 = *(const float4*)&zs[(rb + 1) * LC + lg * 4];
            float4 s2 = *(const float4*)&zs[(rb + 2) * LC + lg * 4];
            float4 s3 = *(const float4*)&zs[(rb + 3) * LC + lg * 4];
            #pragma unroll
            for (int ll = 0; ll < 4; ll++) {
                u64 wv = *(const u64*)&w1s[(lg * 4 + ll) * HC + jp * 2];
                float v0 = ((const float*)&s0)[ll];
                float v1 = ((const float*)&s1)[ll];
                float v2 = ((const float*)&s2)[ll];
                float v3 = ((const float*)&s3)[ll];
                a0 = fma2(pack2(v0, v0), wv, a0);
                a1 = fma2(pack2(v1, v1), wv, a1);
                a2 = fma2(pack2(v2, v2), wv, a2);
                a3 = fma2(pack2(v3, v3), wv, a3);
            }
        }
        size_t base = (size_t)(row0 + rb) * HC + jp * 2;
        if (row0 + rb + 3 < rows) {
            *(u64*)&g_zw1[base + 0 * HC] = a0;
            *(u64*)&g_zw1[base + 1 * HC] = a1;
            *(u64*)&g_zw1[base + 2 * HC] = a2;
            *(u64*)&g_zw1[base + 3 * HC] = a3;
        } else {
            if (row0 + rb + 0 < rows) *(u64*)&g_zw1[base + 0 * HC] = a0;
            if (row0 + rb + 1 < rows) *(u64*)&g_zw1[base + 1 * HC] = a1;
            if (row0 + rb + 2 < rows) *(u64*)&g_zw1[base + 2 * HC] = a2;
        }
    }
}

// ---------------- 2. scatter (scan fused: each block recomputes it) --------
__global__ void scatter_kernel(const int* __restrict__ batch, int n, int B) {
    __shared__ int tmp[BMAX];
    __shared__ int cur[BMAX];
    int tid = threadIdx.x, blk = blockIdx.x;

    int v0 = g_hist[tid];
    tmp[tid] = v0;
    __syncthreads();
    #pragma unroll
    for (int d = 1; d < BMAX; d <<= 1) {
        int v = (tid >= d) ? tmp[tid - d] : 0;
        __syncthreads();
        tmp[tid] += v;
        __syncthreads();
    }
    int start = tmp[tid] - v0;     // exclusive scan
    if (blk == 0) {                // publish for main
        g_binstart[tid] = start;
        g_cnt[tid]      = v0;
    }
    int mine = g_bh[blk * BMAX + tid];
    cur[tid] = start + (mine ? atomicAdd(&g_cur2[tid], mine) : 0);
    __syncthreads();

    int span = (n + NB - 1) / NB;
    int lo = blk * span, hi = min(n, lo + span);
    for (int i = lo + tid; i < hi; i += 256) {
        int b = batch[i];
        if (b < 0 || b >= B) continue;
        int pos = atomicAdd(&cur[b], 1);    // smem atomic
        g_perm[pos] = i;
    }
}

// ---------------- 3. main fused kernel (unchanged from R16) ----------------
__global__ __launch_bounds__(256, 2)
void main_kernel(const float* __restrict__ s, const float* __restrict__ W2,
                 const float* __restrict__ b1, const float* __restrict__ b2,
                 float* __restrict__ out, int B) {
    extern __shared__ __align__(16) float sm[];
    float* zw1s = sm;                        // [k][j]  32x256 = 8192 fl
    float* ss   = zw1s + KC * HC;            // [n][SS]         2304 fl
    float* hbuf = ss + CHUNK * SS;           // [n][HS]        16896 fl
    float* pbuf = hbuf;                      // alias (sync-separated)
    int*   nids = (int*)(hbuf + CHUNK * HS);

    int tid = threadIdx.x;
    if (blockIdx.x == 0) { g_hist[tid] = 0; g_cur2[tid] = 0; }

    int b   = blockIdx.x % B;
    int c0  = blockIdx.x / B;
    int cnt = g_cnt[b];
    if (c0 * CHUNK >= cnt) return;
    int start = g_binstart[b];

    const float4* zw1g = (const float4*)(g_zw1 + (size_t)b * KC * HC);
    #pragma unroll
    for (int i = 0; i < 8; i++)
        ((float4*)zw1s)[tid + i * 256] = zw1g[tid + i * 256];

    int w = tid >> 5, lane = tid & 31;
    int nh = w & 1, jw = w >> 1;
    int ng = lane >> 3, jg = lane & 7;
    int j0 = jw * 64 + jg * 4;
    int j1 = j0 + 32;
    int nrow0 = nh * 32 + ng;

    u64 bq[4];
    {
        float4 v = *(const float4*)&b1[j0];
        bq[0] = pack2(v.x, v.y); bq[1] = pack2(v.z, v.w);
        v = *(const float4*)&b1[j1];
        bq[2] = pack2(v.x, v.y); bq[3] = pack2(v.z, v.w);
    }
    float4 bb = __ldg((const float4*)(b2 + ((tid & 7) * 4)));

    int pfn[2];
    {
        #pragma unroll
        for (int e = 0; e < 2; e++) {
            int i = ((e * 256 + tid) >> 3);
            int gi = c0 * CHUNK + i;
            pfn[e] = (gi < cnt) ? __ldg(g_perm + start + gi) : -1;
        }
    }

    for (int c = c0; c * CHUNK < cnt; c += CPG) {
        __syncthreads();
        #pragma unroll
        for (int e = 0; e < 2; e++) {
            int idx = e * 256 + tid;
            int i = idx >> 3, qq = idx & 7;
            int nid = pfn[e];
            if (qq == 0) nids[i] = nid;
            float4 v = make_float4(0.f, 0.f, 0.f, 0.f);
            if (nid >= 0) v = __ldg((const float4*)(s + (size_t)nid * KC) + qq);
            *(float4*)&ss[i * SS + qq * 4] = v;
        }
        {
            int cn = c + CPG;
            #pragma unroll
            for (int e = 0; e < 2; e++) {
                int i = ((e * 256 + tid) >> 3);
                int gi = cn * CHUNK + i;
                pfn[e] = (cn * CHUNK < cnt && gi < cnt)
                       ? __ldg(g_perm + start + gi) : -1;
            }
        }
        __syncthreads();

        // ================= H phase =================
        u64 ha[8][4];
        #pragma unroll
        for (int t = 0; t < 8; t++) {
            ha[t][0] = bq[0]; ha[t][1] = bq[1];
            ha[t][2] = bq[2]; ha[t][3] = bq[3];
        }
        #pragma unroll
        for (int kg = 0; kg < 8; kg++) {
            float4 s4[8];
            #pragma unroll
            for (int t = 0; t < 8; t++)
                s4[t] = *(const float4*)&ss[(nrow0 + 4 * t) * SS + kg * 4];
            #pragma unroll
            for (int kk = 0; kk < 4; kk++) {
                int k = kg * 4 + kk;
                ulonglong2 wa = *(const ulonglong2*)&zw1s[k * HC + j0];
                ulonglong2 wb = *(const ulonglong2*)&zw1s[k * HC + j1];
                #pragma unroll
                for (int t = 0; t < 8; t++) {
                    float sv = ((const float*)&s4[t])[kk];
                    u64 sp = pack2(sv, sv);
                    ha[t][0] = fma2(sp, wa.x, ha[t][0]);
                    ha[t][1] = fma2(sp, wa.y, ha[t][1]);
                    ha[t][2] = fma2(sp, wb.x, ha[t][2]);
                    ha[t][3] = fma2(sp, wb.y, ha[t][3]);
                }
            }
        }
        #pragma unroll
        for (int t = 0; t < 8; t++) {
            int nt = nrow0 + 4 * t;
            float4 v0, v1; float x, y;
            unpack2(ha[t][0], x, y); v0.x = fmaxf(x,0.f); v0.y = fmaxf(y,0.f);
            unpack2(ha[t][1], x, y); v0.z = fmaxf(x,0.f); v0.w = fmaxf(y,0.f);
            unpack2(ha[t][2], x, y); v1.x = fmaxf(x,0.f); v1.y = fmaxf(y,0.f);
            unpack2(ha[t][3], x, y); v1.z = fmaxf(x,0.f); v1.w = fmaxf(y,0.f);
            *(float4*)&hbuf[nt * HS + j0] = v0;
            *(float4*)&hbuf[nt * HS + j1] = v1;
        }
        __syncthreads();

        // ================= OUT phase (j-quarter q = jw) =================
        u64 acc[8][2];
        #pragma unroll
        for (int t = 0; t < 8; t++) { acc[t][0] = 0ull; acc[t][1] = 0ull; }
        #pragma unroll 4
        for (int j4 = 0; j4 < 16; j4++) {
            int jb = jw * 64 + j4 * 4;
            ulonglong2 w20 = __ldg((const ulonglong2*)(W2 + (jb + 0) * OC + jg * 4));
            ulonglong2 w21 = __ldg((const ulonglong2*)(W2 + (jb + 1) * OC + jg * 4));
            ulonglong2 w22 = __ldg((const ulonglong2*)(W2 + (jb + 2) * OC + jg * 4));
            ulonglong2 w23 = __ldg((const ulonglong2*)(W2 + (jb + 3) * OC + jg * 4));
            #pragma unroll
            for (int t = 0; t < 8; t++) {
                int nt = nrow0 + 4 * t;
                float4 hv = *(const float4*)&hbuf[nt * HS + jb];
                u64 h0 = pack2(hv.x, hv.x), h1 = pack2(hv.y, hv.y);
                u64 h2 = pack2(hv.z, hv.z), h3 = pack2(hv.w, hv.w);
                acc[t][0] = fma2(h0, w20.x, acc[t][0]);
                acc[t][1] = fma2(h0, w20.y, acc[t][1]);
                acc[t][0] = fma2(h1, w21.x, acc[t][0]);
                acc[t][1] = fma2(h1, w21.y, acc[t][1]);
                acc[t][0] = fma2(h2, w22.x, acc[t][0]);
                acc[t][1] = fma2(h2, w22.y, acc[t][1]);
                acc[t][0] = fma2(h3, w23.x, acc[t][0]);
                acc[t][1] = fma2(h3, w23.y, acc[t][1]);
            }
        }
        __syncthreads();
        #pragma unroll
        for (int t = 0; t < 8; t++) {
            int nt = nrow0 + 4 * t;
            float4 v;
            unpack2(acc[t][0], v.x, v.y);
            unpack2(acc[t][1], v.z, v.w);
            *(float4*)&pbuf[(jw * CHUNK + nt) * PS + jg * 4] = v;
        }
        __syncthreads();

        #pragma unroll
        for (int e = 0; e < 2; e++) {
            int idx = e * 256 + tid;
            int nn = idx >> 3, oo = (idx & 7) * 4;
            int nid = nids[nn];
            if (nid >= 0) {
                float4 r  = *(const float4*)&pbuf[(0 * CHUNK + nn) * PS + oo];
                float4 p1 = *(const float4*)&pbuf[(1 * CHUNK + nn) * PS + oo];
                float4 p2 = *(const float4*)&pbuf[(2 * CHUNK + nn) * PS + oo];
                float4 p3 = *(const float4*)&pbuf[(3 * CHUNK + nn) * PS + oo];
                r.x += p1.x + p2.x + p3.x + bb.x;
                r.y += p1.y + p2.y + p3.y + bb.y;
                r.z += p1.z + p2.z + p3.z + bb.z;
                r.w += p1.w + p2.w + p3.w + bb.w;
                *(float4*)(out + (size_t)nid * OC + oo) = r;
            }
        }
    }
}

// ---------------- launch ----------------------------------------------------
extern "C" void kernel_launch(void* const* d_in, const int* in_sizes, int n_in,
                              void* d_out, int out_size) {
    const float* z     = (const float*)d_in[0];
    const float* s     = (const float*)d_in[1];
    const int*   batch = (const int*)d_in[2];   // JAX x64 disabled -> int32
    const float* W1    = (const float*)d_in[3];
    const float* b1    = (const float*)d_in[4];
    const float* W2    = (const float*)d_in[5];
    const float* b2    = (const float*)d_in[6];
    float*       out   = (float*)d_out;

    int n = in_sizes[2];
    int B = in_sizes[0] / (KC * LC);
    int zb2 = (B * KC + ZROWS - 1) / ZROWS;

    cudaFuncSetAttribute(prep_kernel,
        cudaFuncAttributeMaxDynamicSharedMemorySize, PREP_SMEM);
    cudaFuncSetAttribute(main_kernel,
        cudaFuncAttributeMaxDynamicSharedMemorySize, MAIN_SMEM);

    prep_kernel<<<zb2 + NB, 256, PREP_SMEM>>>(z, W1, batch, n, B, zb2);
    scatter_kernel<<<NB, 256>>>(batch, n, B);
    main_kernel<<<B * CPG, 256, MAIN_SMEM>>>(s, W2, b1, b2, out, B);
}